// round 8
// baseline (speedup 1.0000x reference)
#include <cuda_runtime.h>
#include <cuda_bf16.h>

// Problem constants
#define B_  8
#define C_  256
#define O_  256
#define H_  64
#define W_  64
#define HW_ 4096
#define KK_ 9
#define P_  64   // positions per CTA = one full image row

// Small static scratch only (tight device-memory margin on this container):
// weight retiled to [kk][c][o] = 2.25 MiB.
__device__ float g_wT[KK_ * C_ * O_];

// ---------------------------------------------------------------------------
// packed fp32x2 helpers (sm_103a: fma.rn.f32x2 = 2 FMAs per issue slot)
// ---------------------------------------------------------------------------
__device__ __forceinline__ unsigned long long pk2(float v) {
    unsigned long long r;
    asm("mov.b64 %0, {%1, %1};" : "=l"(r) : "f"(v));
    return r;
}
__device__ __forceinline__ void fma2(unsigned long long& d,
                                     unsigned long long a,
                                     unsigned long long b) {
    asm("fma.rn.f32x2 %0, %1, %2, %0;" : "+l"(d) : "l"(a), "l"(b));
}
__device__ __forceinline__ float2 upk2(unsigned long long v) {
    float2 r;
    asm("mov.b64 {%0, %1}, %2;" : "=f"(r.x), "=f"(r.y) : "l"(v));
    return r;
}

// ---------------------------------------------------------------------------
// Kernel 1: weight (O,C,3,3) -> wT[kk][c][o]
// ---------------------------------------------------------------------------
__global__ void dcn_transpose_w(const float* __restrict__ w) {
    int i = blockIdx.x * 256 + threadIdx.x;
    if (i >= KK_ * C_ * O_) return;
    int kk  = i >> 16;
    int rem = i & 65535;
    int c = rem >> 8;
    int o = rem & 255;
    g_wT[i] = w[o * 2304 + c * 9 + kk];
}

// ---------------------------------------------------------------------------
// Kernel 2: fused bilinear-im2col + GEMM.
// CTA: one full row (64 hw positions) x all 256 out channels.
// Per (kk, c-chunk of 32): stage w tile (32 KB) + gather s tile (32c x 64p),
// then 8o x 8p register-tiled GEMM with packed f32x2 FMAs (packed over o).
// L1-bandwidth-optimized: per c-iter per thread only 4x LDS.128.
// ---------------------------------------------------------------------------
__global__ __launch_bounds__(256, 2)
void dcn_main(const float* __restrict__ x,      // (B, C, H, W)
              const float* __restrict__ coff,   // (B, 2*KK, H, W)
              const float* __restrict__ cwt,    // (B, KK, H, W)
              const float* __restrict__ bias,   // (O)
              float* __restrict__ out)          // (B, O, H, W)
{
    __shared__ float w_sm[32 * 256];    // [c_local][o]       32 KB
    __shared__ float s_sm[32 * 68];     // [c_local][p] pad68 8.7 KB (16B-aligned rows)
    __shared__ int   pspat_sm[P_ * 5];  // 4 corner spatial indices, stride-5 pad
    __shared__ float pwgt_sm[P_ * 5];   // folded bilinear*coord_weight (0 if OOB)

    const int cta = blockIdx.x;         // 512 CTAs
    const int b   = cta >> 6;           // 64 CTAs (rows) per batch
    const int y   = cta & 63;           // image row
    const int p0  = y << 6;             // hw base of this row

    const int tid  = threadIdx.x;
    const int wrp  = tid >> 5;          // warp 0..7
    const int lane = tid & 31;
    const int to   = tid >> 3;          // GEMM: o_base = to*8 (0..31)
    const int tp   = tid & 7;           // GEMM: p_base = tp*8 (0..7)

    const float* xbb = x + (b << 20);   // batch base: b*C*HW

    unsigned long long acc[4][8];       // [o-pair-quad via wA/wB][p]
#pragma unroll
    for (int i = 0; i < 4; ++i)
#pragma unroll
        for (int j = 0; j < 8; ++j) acc[i][j] = 0ull;

    for (int kk = 0; kk < KK_; ++kk) {
        // ---- per-tap per-position bilinear prep (threads 0..63) ----
        if (tid < P_) {
            int xx = tid;
            int base_oy = ((b * 18 + 2 * kk) * 64 + y) * 64 + xx;
            float oy = __ldg(&coff[base_oy]);
            float ox = __ldg(&coff[base_oy + HW_]);
            float cw = __ldg(&cwt[((b * 9 + kk) * 64 + y) * 64 + xx]);
            int ky = kk / 3;
            int kx = kk - ky * 3;
            float py = (float)(y  - 1 + ky) + oy;
            float px = (float)(xx - 1 + kx) + ox;
            float fy = floorf(py), fx = floorf(px);
            int   y0 = (int)fy,    x0 = (int)fx;
            float wy1 = py - fy, wy0 = 1.0f - wy1;
            float wx1 = px - fx, wx0 = 1.0f - wx1;
            bool vy0 = (y0 >= 0)  && (y0 < H_);
            bool vy1 = (y0 >= -1) && (y0 < H_ - 1);
            bool vx0 = (x0 >= 0)  && (x0 < W_);
            bool vx1 = (x0 >= -1) && (x0 < W_ - 1);
            int yc0 = max(0, min(H_ - 1, y0));
            int yc1 = max(0, min(H_ - 1, y0 + 1));
            int xc0 = max(0, min(W_ - 1, x0));
            int xc1 = max(0, min(W_ - 1, x0 + 1));
            pspat_sm[tid * 5 + 0] = (yc0 << 6) + xc0;
            pspat_sm[tid * 5 + 1] = (yc0 << 6) + xc1;
            pspat_sm[tid * 5 + 2] = (yc1 << 6) + xc0;
            pspat_sm[tid * 5 + 3] = (yc1 << 6) + xc1;
            pwgt_sm[tid * 5 + 0] = (vy0 && vx0) ? cw * wy0 * wx0 : 0.0f;
            pwgt_sm[tid * 5 + 1] = (vy0 && vx1) ? cw * wy0 * wx1 : 0.0f;
            pwgt_sm[tid * 5 + 2] = (vy1 && vx0) ? cw * wy1 * wx0 : 0.0f;
            pwgt_sm[tid * 5 + 3] = (vy1 && vx1) ? cw * wy1 * wx1 : 0.0f;
        }
        __syncthreads();

        // each gather lane caches corner state for its 2 positions (p, p+32)
        int   sp[2][4];
        float gw[2][4];
#pragma unroll
        for (int h = 0; h < 2; ++h) {
            int p = lane + (h << 5);
#pragma unroll
            for (int j = 0; j < 4; ++j) {
                sp[h][j] = pspat_sm[p * 5 + j];
                gw[h][j] = pwgt_sm[p * 5 + j];
            }
        }

        for (int cc = 0; cc < 8; ++cc) {
            __syncthreads();   // previous GEMM done with s_sm/w_sm

            // ---- stage weight chunk: wT[kk][cc*32..+32][0..255] (contiguous) ----
            {
                const float4* wsrc =
                    (const float4*)(g_wT + (kk << 16) + (cc << 13));
                float4* wdst = (float4*)w_sm;
#pragma unroll
                for (int i = 0; i < 8; ++i)
                    wdst[tid + (i << 8)] = wsrc[tid + (i << 8)];
            }

            // ---- gather s tile: warp w -> c_local = w*4..+3, lane covers p,p+32 ----
            {
                int c_lo = (wrp << 2);
#pragma unroll
                for (int i = 0; i < 4; ++i) {
                    const float* pl = xbb + (((cc << 5) + c_lo + i) << 12);
#pragma unroll
                    for (int h = 0; h < 2; ++h) {
                        float v = gw[h][0] * __ldg(pl + sp[h][0])
                                + gw[h][1] * __ldg(pl + sp[h][1])
                                + gw[h][2] * __ldg(pl + sp[h][2])
                                + gw[h][3] * __ldg(pl + sp[h][3]);
                        s_sm[(c_lo + i) * 68 + (h << 5) + lane] = v;
                    }
                }
            }
            __syncthreads();

            // ---- GEMM: acc[o=to*8..+7][p=tp*8..+7] += w[c][o] * s[c][p] ----
            const ulonglong2* wq = (const ulonglong2*)w_sm;  // [c][64 x ull2]
#pragma unroll 2
            for (int c = 0; c < 32; ++c) {
                ulonglong2 wA = wq[(c << 6) + (to << 1)];      // o pairs 0-1,2-3
                ulonglong2 wB = wq[(c << 6) + (to << 1) + 1];  // o pairs 4-5,6-7
                const float4* s4 = (const float4*)(s_sm + c * 68 + (tp << 3));
                float4 f0 = s4[0];
                float4 f1 = s4[1];
                unsigned long long s0 = pk2(f0.x), s1 = pk2(f0.y);
                unsigned long long s2 = pk2(f0.z), s3 = pk2(f0.w);
                unsigned long long s4r = pk2(f1.x), s5 = pk2(f1.y);
                unsigned long long s6 = pk2(f1.z), s7 = pk2(f1.w);
                fma2(acc[0][0], wA.x, s0);  fma2(acc[0][1], wA.x, s1);
                fma2(acc[0][2], wA.x, s2);  fma2(acc[0][3], wA.x, s3);
                fma2(acc[0][4], wA.x, s4r); fma2(acc[0][5], wA.x, s5);
                fma2(acc[0][6], wA.x, s6);  fma2(acc[0][7], wA.x, s7);
                fma2(acc[1][0], wA.y, s0);  fma2(acc[1][1], wA.y, s1);
                fma2(acc[1][2], wA.y, s2);  fma2(acc[1][3], wA.y, s3);
                fma2(acc[1][4], wA.y, s4r); fma2(acc[1][5], wA.y, s5);
                fma2(acc[1][6], wA.y, s6);  fma2(acc[1][7], wA.y, s7);
                fma2(acc[2][0], wB.x, s0);  fma2(acc[2][1], wB.x, s1);
                fma2(acc[2][2], wB.x, s2);  fma2(acc[2][3], wB.x, s3);
                fma2(acc[2][4], wB.x, s4r); fma2(acc[2][5], wB.x, s5);
                fma2(acc[2][6], wB.x, s6);  fma2(acc[2][7], wB.x, s7);
                fma2(acc[3][0], wB.y, s0);  fma2(acc[3][1], wB.y, s1);
                fma2(acc[3][2], wB.y, s2);  fma2(acc[3][3], wB.y, s3);
                fma2(acc[3][4], wB.y, s4r); fma2(acc[3][5], wB.y, s5);
                fma2(acc[3][6], wB.y, s6);  fma2(acc[3][7], wB.y, s7);
            }
        }
    }

    // ---- epilogue: unpack, add bias, coalesced float4 stores ----
    const int o0 = to << 3;
#pragma unroll
    for (int i = 0; i < 4; ++i) {
        float2 a[8];
#pragma unroll
        for (int j = 0; j < 8; ++j) a[j] = upk2(acc[i][j]);
        int oA = o0 + (i << 1);
        int oB = oA + 1;
        float bA = bias[oA];
        float bB = bias[oB];
        float4 vA0 = make_float4(a[0].x + bA, a[1].x + bA, a[2].x + bA, a[3].x + bA);
        float4 vA1 = make_float4(a[4].x + bA, a[5].x + bA, a[6].x + bA, a[7].x + bA);
        float4 vB0 = make_float4(a[0].y + bB, a[1].y + bB, a[2].y + bB, a[3].y + bB);
        float4 vB1 = make_float4(a[4].y + bB, a[5].y + bB, a[6].y + bB, a[7].y + bB);
        float* oa = out + (((b << 8) + oA) << 12) + p0 + (tp << 3);
        float* ob = out + (((b << 8) + oB) << 12) + p0 + (tp << 3);
        *(float4*)(oa)     = vA0;
        *(float4*)(oa + 4) = vA1;
        *(float4*)(ob)     = vB0;
        *(float4*)(ob + 4) = vB1;
    }
}

// ---------------------------------------------------------------------------
// Launch: inputs per metadata order: input, coord_offset, coord_weight, weight, bias
// ---------------------------------------------------------------------------
extern "C" void kernel_launch(void* const* d_in, const int* in_sizes, int n_in,
                              void* d_out, int out_size) {
    const float* x    = (const float*)d_in[0];
    const float* coff = (const float*)d_in[1];
    const float* cwt  = (const float*)d_in[2];
    const float* wt   = (const float*)d_in[3];
    const float* bias = (const float*)d_in[4];
    float* out = (float*)d_out;

    dcn_transpose_w<<<(KK_ * C_ * O_ + 255) / 256, 256>>>(wt);
    dcn_main<<<B_ * HW_ / P_, 256>>>(x, coff, cwt, bias, out);
}

// round 9
// speedup vs baseline: 1.0160x; 1.0160x over previous
#include <cuda_runtime.h>
#include <cuda_bf16.h>

// Problem constants
#define B_  8
#define C_  256
#define O_  256
#define H_  64
#define W_  64
#define HW_ 4096
#define KK_ 9
#define P_  32   // positions per CTA

// Small static scratch only: weight retiled to [kk][c][o] = 2.25 MiB.
__device__ float g_wT[KK_ * C_ * O_];

// ---------------------------------------------------------------------------
// packed fp32x2 helpers (sm_103a: fma.rn.f32x2 = 2 FMAs per issue slot)
// ---------------------------------------------------------------------------
__device__ __forceinline__ unsigned long long pk2(float v) {
    unsigned long long r;
    asm("mov.b64 %0, {%1, %1};" : "=l"(r) : "f"(v));
    return r;
}
__device__ __forceinline__ void fma2(unsigned long long& d,
                                     unsigned long long a,
                                     unsigned long long b) {
    asm("fma.rn.f32x2 %0, %1, %2, %0;" : "+l"(d) : "l"(a), "l"(b));
}
__device__ __forceinline__ float2 upk2(unsigned long long v) {
    float2 r;
    asm("mov.b64 {%0, %1}, %2;" : "=f"(r.x), "=f"(r.y) : "l"(v));
    return r;
}

// ---------------------------------------------------------------------------
// Kernel 1: weight (O,C,3,3) -> wT[kk][c][o]
// ---------------------------------------------------------------------------
__global__ void dcn_transpose_w(const float* __restrict__ w) {
    int i = blockIdx.x * 256 + threadIdx.x;
    if (i >= KK_ * C_ * O_) return;
    int kk  = i >> 16;
    int rem = i & 65535;
    int c = rem >> 8;
    int o = rem & 255;
    g_wT[i] = w[o * 2304 + c * 9 + kk];
}

// ---------------------------------------------------------------------------
// Kernel 2: fused bilinear-im2col + GEMM, software-pipelined.
// CTA: 32 hw positions x 256 out channels. 72 stages = 9 taps x 8 c-chunks.
// Stage s: issue gather LDGs for stage s+1, GEMM stage s (hides LDG latency),
// barrier, combine+STS into the other s-buffer, stage next w chunk, barrier.
// GEMM inner loop is byte-identical to the proven R7 mix.
// ---------------------------------------------------------------------------
__global__ __launch_bounds__(256, 2)
void dcn_main(const float* __restrict__ x,      // (B, C, H, W)
              const float* __restrict__ coff,   // (B, 2*KK, H, W)
              const float* __restrict__ cwt,    // (B, KK, H, W)
              const float* __restrict__ bias,   // (O)
              float* __restrict__ out)          // (B, O, H, W)
{
    __shared__ float w_sm[32 * 256];          // [c_local][o]        32768 B
    __shared__ float s_sm[2][32 * 33];        // double-buffered      8448 B
    __shared__ float pwgt_all[KK_ * 4 * 32];  // [kk][corner][p]      4608 B
    __shared__ int   pspat_all[KK_ * 2 * 32]; // [kk][pair][p] packed 2304 B
                                              // total               48128 B

    const int cta = blockIdx.x;          // 1024 CTAs
    const int b   = cta >> 7;            // 128 CTAs per batch
    const int p0  = (cta & 127) << 5;    // hw base (one row segment)
    const int y   = p0 >> 6;
    const int xb  = p0 & 63;

    const int tid = threadIdx.x;
    const int wrp = tid >> 5;            // warp 0..7
    const int p   = tid & 31;            // gather lane = position
    const int to  = tid >> 3;            // GEMM: o_base = to*8
    const int tp  = tid & 7;             // GEMM: p_base = tp*4

    const float* xbb = x + (b << 20);    // batch base
    const int c_lo = wrp << 2;           // this warp's c_local base (4 planes)

    // ---- one-time prep of ALL taps: corner indices (packed) + folded weights
    for (int i = tid; i < KK_ * 32; i += 256) {
        int kk = i >> 5;
        int pp = i & 31;
        int xx = xb + pp;
        int base_oy = ((b * 18 + 2 * kk) * 64 + y) * 64 + xx;
        float oy = __ldg(&coff[base_oy]);
        float ox = __ldg(&coff[base_oy + HW_]);
        float cw = __ldg(&cwt[((b * 9 + kk) * 64 + y) * 64 + xx]);
        int ky = kk / 3;
        int kx = kk - ky * 3;
        float py = (float)(y  - 1 + ky) + oy;
        float px = (float)(xx - 1 + kx) + ox;
        float fy = floorf(py), fx = floorf(px);
        int   y0 = (int)fy,    x0 = (int)fx;
        float wy1 = py - fy, wy0 = 1.0f - wy1;
        float wx1 = px - fx, wx0 = 1.0f - wx1;
        bool vy0 = (y0 >= 0)  && (y0 < H_);
        bool vy1 = (y0 >= -1) && (y0 < H_ - 1);
        bool vx0 = (x0 >= 0)  && (x0 < W_);
        bool vx1 = (x0 >= -1) && (x0 < W_ - 1);
        int yc0 = max(0, min(H_ - 1, y0));
        int yc1 = max(0, min(H_ - 1, y0 + 1));
        int xc0 = max(0, min(W_ - 1, x0));
        int xc1 = max(0, min(W_ - 1, x0 + 1));
        int s0 = (yc0 << 6) + xc0, s1 = (yc0 << 6) + xc1;
        int s2 = (yc1 << 6) + xc0, s3 = (yc1 << 6) + xc1;
        pspat_all[(kk << 6) + pp]      = s0 | (s1 << 16);
        pspat_all[(kk << 6) + 32 + pp] = s2 | (s3 << 16);
        pwgt_all[(kk << 7) + pp]       = (vy0 && vx0) ? cw * wy0 * wx0 : 0.0f;
        pwgt_all[(kk << 7) + 32 + pp]  = (vy0 && vx1) ? cw * wy0 * wx1 : 0.0f;
        pwgt_all[(kk << 7) + 64 + pp]  = (vy1 && vx0) ? cw * wy1 * wx0 : 0.0f;
        pwgt_all[(kk << 7) + 96 + pp]  = (vy1 && vx1) ? cw * wy1 * wx1 : 0.0f;
    }
    __syncthreads();

    unsigned long long acc[4][4];
#pragma unroll
    for (int i = 0; i < 4; ++i)
#pragma unroll
        for (int j = 0; j < 4; ++j) acc[i][j] = 0ull;

    // ---- prologue: gather + stage stage-0 tiles (kk=0, cc=0) ----
    {
        int pk01 = pspat_all[p];
        int pk23 = pspat_all[32 + p];
        int sp0 = pk01 & 0xFFFF, sp1 = ((unsigned)pk01) >> 16;
        int sp2 = pk23 & 0xFFFF, sp3 = ((unsigned)pk23) >> 16;
        float g0 = pwgt_all[p],      g1 = pwgt_all[32 + p];
        float g2 = pwgt_all[64 + p], g3 = pwgt_all[96 + p];
#pragma unroll
        for (int i = 0; i < 4; ++i) {
            const float* pl = xbb + ((c_lo + i) << 12);
            float v = g0 * __ldg(pl + sp0) + g1 * __ldg(pl + sp1)
                    + g2 * __ldg(pl + sp2) + g3 * __ldg(pl + sp3);
            s_sm[0][(c_lo + i) * 33 + p] = v;
        }
        const float4* wsrc = (const float4*)g_wT;
        float4* wdst = (float4*)w_sm;
#pragma unroll
        for (int i = 0; i < 8; ++i)
            wdst[tid + (i << 8)] = wsrc[tid + (i << 8)];
    }
    __syncthreads();

    // ---- 72 pipelined stages ----
    for (int s = 0; s < 72; ++s) {
        const int buf = s & 1;
        const int sn  = s + 1;
        const int kk2 = sn >> 3;      // next-stage tap
        const int cc2 = sn & 7;       // next-stage c-chunk

        // issue next stage's gather loads (latency hidden by GEMM below)
        float ld[16];
        if (s < 71) {
            int pk01 = pspat_all[(kk2 << 6) + p];
            int pk23 = pspat_all[(kk2 << 6) + 32 + p];
            int sp0 = pk01 & 0xFFFF, sp1 = ((unsigned)pk01) >> 16;
            int sp2 = pk23 & 0xFFFF, sp3 = ((unsigned)pk23) >> 16;
#pragma unroll
            for (int i = 0; i < 4; ++i) {
                const float* pl = xbb + (((cc2 << 5) + c_lo + i) << 12);
                ld[i * 4 + 0] = __ldg(pl + sp0);
                ld[i * 4 + 1] = __ldg(pl + sp1);
                ld[i * 4 + 2] = __ldg(pl + sp2);
                ld[i * 4 + 3] = __ldg(pl + sp3);
            }
        }

        // ---- GEMM on current buffers (identical to R7 inner loop) ----
        const ulonglong2* wq = (const ulonglong2*)w_sm;
        const float* sbase = s_sm[buf];
#pragma unroll 4
        for (int c = 0; c < 32; ++c) {
            ulonglong2 wA = wq[(c << 6) + (to << 1)];
            ulonglong2 wB = wq[(c << 6) + (to << 1) + 1];
            const float* srow = sbase + c * 33 + (tp << 2);
            unsigned long long s0 = pk2(srow[0]);
            unsigned long long s1 = pk2(srow[1]);
            unsigned long long s2 = pk2(srow[2]);
            unsigned long long s3 = pk2(srow[3]);
            fma2(acc[0][0], wA.x, s0); fma2(acc[0][1], wA.x, s1);
            fma2(acc[0][2], wA.x, s2); fma2(acc[0][3], wA.x, s3);
            fma2(acc[1][0], wA.y, s0); fma2(acc[1][1], wA.y, s1);
            fma2(acc[1][2], wA.y, s2); fma2(acc[1][3], wA.y, s3);
            fma2(acc[2][0], wB.x, s0); fma2(acc[2][1], wB.x, s1);
            fma2(acc[2][2], wB.x, s2); fma2(acc[2][3], wB.x, s3);
            fma2(acc[3][0], wB.y, s0); fma2(acc[3][1], wB.y, s1);
            fma2(acc[3][2], wB.y, s2); fma2(acc[3][3], wB.y, s3);
        }
        __syncthreads();   // GEMM done: w_sm and s_sm[1-buf] are free

        if (s < 71) {
            // combine + store gathered tile into the other s-buffer
            float g0 = pwgt_all[(kk2 << 7) + p];
            float g1 = pwgt_all[(kk2 << 7) + 32 + p];
            float g2 = pwgt_all[(kk2 << 7) + 64 + p];
            float g3 = pwgt_all[(kk2 << 7) + 96 + p];
#pragma unroll
            for (int i = 0; i < 4; ++i) {
                float v = g0 * ld[i * 4 + 0] + g1 * ld[i * 4 + 1]
                        + g2 * ld[i * 4 + 2] + g3 * ld[i * 4 + 3];
                s_sm[1 - buf][(c_lo + i) * 33 + p] = v;
            }
            // stage next weight chunk (L2-resident, short exposure)
            const float4* wsrc =
                (const float4*)(g_wT + (kk2 << 16) + (cc2 << 13));
            float4* wdst = (float4*)w_sm;
#pragma unroll
            for (int i = 0; i < 8; ++i)
                wdst[tid + (i << 8)] = wsrc[tid + (i << 8)];
        }
        __syncthreads();   // next-stage buffers ready
    }

    // ---- epilogue: unpack, add bias, coalesced float4 stores ----
    const int o0 = to << 3;
#pragma unroll
    for (int oo = 0; oo < 4; ++oo) {
        float2 a0 = upk2(acc[oo][0]);
        float2 a1 = upk2(acc[oo][1]);
        float2 a2 = upk2(acc[oo][2]);
        float2 a3 = upk2(acc[oo][3]);
        int oA = o0 + (oo << 1);
        int oB = oA + 1;
        float bA = bias[oA];
        float bB = bias[oB];
        float4 vA = make_float4(a0.x + bA, a1.x + bA, a2.x + bA, a3.x + bA);
        float4 vB = make_float4(a0.y + bB, a1.y + bB, a2.y + bB, a3.y + bB);
        *(float4*)(out + ((((b << 8) + oA) << 12) + p0 + (tp << 2))) = vA;
        *(float4*)(out + ((((b << 8) + oB) << 12) + p0 + (tp << 2))) = vB;
    }
}

// ---------------------------------------------------------------------------
// Launch: inputs per metadata order: input, coord_offset, coord_weight, weight, bias
// ---------------------------------------------------------------------------
extern "C" void kernel_launch(void* const* d_in, const int* in_sizes, int n_in,
                              void* d_out, int out_size) {
    const float* x    = (const float*)d_in[0];
    const float* coff = (const float*)d_in[1];
    const float* cwt  = (const float*)d_in[2];
    const float* wt   = (const float*)d_in[3];
    const float* bias = (const float*)d_in[4];
    float* out = (float*)d_out;

    dcn_transpose_w<<<(KK_ * C_ * O_ + 255) / 256, 256>>>(wt);
    dcn_main<<<B_ * HW_ / P_, 256>>>(x, coff, cwt, bias, out);
}

// round 10
// speedup vs baseline: 1.3239x; 1.3031x over previous
#include <cuda_runtime.h>
#include <cuda_bf16.h>

// Problem constants
#define B_  8
#define C_  256
#define O_  256
#define H_  64
#define W_  64
#define HW_ 4096
#define KK_ 9

// Static scratch: weight pre-split to bf16 hi/lo, retiled [kk][o][c].
// 2 x 1.125 MiB (kept small: container has tight device-memory margin).
__device__ __nv_bfloat16 g_wh[KK_ * O_ * C_];
__device__ __nv_bfloat16 g_wl[KK_ * O_ * C_];

__device__ __forceinline__ unsigned smem_u32(const void* p) {
    unsigned r;
    asm("{ .reg .u64 t; cvta.to.shared.u64 t, %1; cvt.u32.u64 %0, t; }"
        : "=r"(r) : "l"(p));
    return r;
}
__device__ __forceinline__ unsigned pkbf(__nv_bfloat16 a, __nv_bfloat16 b) {
    return (unsigned)__bfloat16_as_ushort(a) |
           ((unsigned)__bfloat16_as_ushort(b) << 16);
}

// ---------------------------------------------------------------------------
// Kernel 1: weight (O,C,3,3) fp32 -> [kk][o][c] bf16 hi + lo (exact residual)
// ---------------------------------------------------------------------------
__global__ void dcn_split_w(const float* __restrict__ w) {
    int i = blockIdx.x * 256 + threadIdx.x;
    if (i >= KK_ * O_ * C_) return;
    int kk = i >> 16;
    int o  = (i >> 8) & 255;
    int c  = i & 255;
    float v = w[o * 2304 + c * 9 + kk];
    __nv_bfloat16 hi = __float2bfloat16_rn(v);
    __nv_bfloat16 lo = __float2bfloat16_rn(v - __bfloat162float(hi));
    g_wh[i] = hi;
    g_wl[i] = lo;
}

// ---------------------------------------------------------------------------
// Kernel 2: fused bilinear-im2col + bf16 tensor-core GEMM (3-term split).
// CTA: one image row (64 p) x 256 o.  144 stages = 9 taps x 16 c-chunks of 16.
// Per stage: stage w [256o][16c] hi/lo + gather s [64p][16c] hi/lo, then each
// warp does 12 ldmatrix.x4 + 48 mma.sync.m16n8k16 (D += Ah*Bh + Al*Bh + Ah*Bl).
// smem rows padded to 48B -> conflict-free ldmatrix phases.
// ---------------------------------------------------------------------------
__global__ __launch_bounds__(256, 2)
void dcn_main(const float* __restrict__ x,      // (B, C, H, W)
              const float* __restrict__ coff,   // (B, 2*KK, H, W)
              const float* __restrict__ cwt,    // (B, KK, H, W)
              const float* __restrict__ bias,   // (O)
              float* __restrict__ out)          // (B, O, H, W)
{
    __shared__ __nv_bfloat16 w_sm[2][256 * 24];  // [split][o][16c+8pad] 24576 B
    __shared__ __nv_bfloat16 s_sm[2][64 * 24];   // [split][p][16c+8pad]  6144 B
    __shared__ float pwgt[KK_ * 4 * 64];         //                       9216 B
    __shared__ int   pspat[KK_ * 2 * 64];        // packed corner pairs   4608 B

    const int cta = blockIdx.x;        // 512 CTAs
    const int b   = cta >> 6;
    const int y   = cta & 63;

    const int tid  = threadIdx.x;
    const int wrp  = tid >> 5;
    const int lane = tid & 31;
    const int ow   = wrp & 3;          // o-group: o_base = ow*64
    const int pw   = wrp >> 2;         // p-group: p_base = pw*32

    const float* xbb = x + ((long)b << 20);

    // ---- one-time prep: all taps' corner indices + folded weights ----
    for (int i = tid; i < KK_ * 64; i += 256) {
        int kk = i >> 6;
        int pp = i & 63;
        int base_oy = ((b * 18 + 2 * kk) * 64 + y) * 64 + pp;
        float oy = __ldg(&coff[base_oy]);
        float ox = __ldg(&coff[base_oy + HW_]);
        float cw = __ldg(&cwt[((b * 9 + kk) * 64 + y) * 64 + pp]);
        int ky = kk / 3;
        int kx = kk - ky * 3;
        float py = (float)(y  - 1 + ky) + oy;
        float px = (float)(pp - 1 + kx) + ox;
        float fy = floorf(py), fx = floorf(px);
        int   y0 = (int)fy,    x0 = (int)fx;
        float wy1 = py - fy, wy0 = 1.0f - wy1;
        float wx1 = px - fx, wx0 = 1.0f - wx1;
        bool vy0 = (y0 >= 0)  && (y0 < H_);
        bool vy1 = (y0 >= -1) && (y0 < H_ - 1);
        bool vx0 = (x0 >= 0)  && (x0 < W_);
        bool vx1 = (x0 >= -1) && (x0 < W_ - 1);
        int yc0 = max(0, min(H_ - 1, y0));
        int yc1 = max(0, min(H_ - 1, y0 + 1));
        int xc0 = max(0, min(W_ - 1, x0));
        int xc1 = max(0, min(W_ - 1, x0 + 1));
        int s0 = (yc0 << 6) + xc0, s1 = (yc0 << 6) + xc1;
        int s2 = (yc1 << 6) + xc0, s3 = (yc1 << 6) + xc1;
        pspat[(kk << 7) + pp]      = s0 | (s1 << 16);
        pspat[(kk << 7) + 64 + pp] = s2 | (s3 << 16);
        pwgt[(kk << 8) + pp]        = (vy0 && vx0) ? cw * wy0 * wx0 : 0.0f;
        pwgt[(kk << 8) + 64 + pp]   = (vy0 && vx1) ? cw * wy0 * wx1 : 0.0f;
        pwgt[(kk << 8) + 128 + pp]  = (vy1 && vx0) ? cw * wy1 * wx0 : 0.0f;
        pwgt[(kk << 8) + 192 + pp]  = (vy1 && vx1) ? cw * wy1 * wx1 : 0.0f;
    }
    __syncthreads();

    float acc[2][8][4];                // [p-tile][o-tile][frag]
#pragma unroll
    for (int i = 0; i < 2; ++i)
#pragma unroll
        for (int j = 0; j < 8; ++j)
#pragma unroll
            for (int k = 0; k < 4; ++k) acc[i][j][k] = 0.0f;

    // gather role: lane-within-2-warps = position, upper bits = c sub-group
    const int gp = tid & 63;           // position 0..63
    const int gc = tid >> 6;           // c sub-group 0..3 (4 c's each)

    // A-fragment ldmatrix addresses (depend only on lane/warp): row-major [p][c]
    // mats: p0-7|c0, p8-15|c0, p0-7|c8, p8-15|c8
    const int a_row_off = (lane & 15);        // row within 16-row tile
    const int a_col_off = (lane >> 4) << 3;   // 0 or 8
    // B-fragment x4 covers 2 o-tiles: mats: o0-7|c0, o0-7|c8, o8-15|c0, o8-15|c8
    const int b_row_off = ((lane >> 4) << 3) + (lane & 7);  // o row within 16
    const int b_col_off = ((lane >> 3) & 1) << 3;           // 0 or 8

    for (int s = 0; s < 144; ++s) {
        const int kk = s >> 4;
        const int c0 = (s & 15) << 4;

        // ---- stage weights: [256o][16c] hi/lo, rows padded to 24 elems ----
        {
            const uint4* src_h = (const uint4*)(g_wh + (kk << 16) + (tid << 8) + c0);
            const uint4* src_l = (const uint4*)(g_wl + (kk << 16) + (tid << 8) + c0);
            uint4* dst_h = (uint4*)(w_sm[0] + tid * 24);
            uint4* dst_l = (uint4*)(w_sm[1] + tid * 24);
            dst_h[0] = src_h[0]; dst_h[1] = src_h[1];
            dst_l[0] = src_l[0]; dst_l[1] = src_l[1];
        }

        // ---- gather s tile: thread -> (p=gp, c = c0+gc*4 .. +3) ----
        {
            int pk01 = pspat[(kk << 7) + gp];
            int pk23 = pspat[(kk << 7) + 64 + gp];
            int sp0 = pk01 & 0xFFFF, sp1 = ((unsigned)pk01) >> 16;
            int sp2 = pk23 & 0xFFFF, sp3 = ((unsigned)pk23) >> 16;
            float g0 = pwgt[(kk << 8) + gp];
            float g1 = pwgt[(kk << 8) + 64 + gp];
            float g2 = pwgt[(kk << 8) + 128 + gp];
            float g3 = pwgt[(kk << 8) + 192 + gp];
            __nv_bfloat16 hv[4], lv[4];
#pragma unroll
            for (int j = 0; j < 4; ++j) {
                const float* pl = xbb + ((c0 + (gc << 2) + j) << 12);
                float v = g0 * __ldg(pl + sp0) + g1 * __ldg(pl + sp1)
                        + g2 * __ldg(pl + sp2) + g3 * __ldg(pl + sp3);
                hv[j] = __float2bfloat16_rn(v);
                lv[j] = __float2bfloat16_rn(v - __bfloat162float(hv[j]));
            }
            uint2 uh = make_uint2(pkbf(hv[0], hv[1]), pkbf(hv[2], hv[3]));
            uint2 ul = make_uint2(pkbf(lv[0], lv[1]), pkbf(lv[2], lv[3]));
            *(uint2*)(s_sm[0] + gp * 24 + (gc << 2)) = uh;
            *(uint2*)(s_sm[1] + gp * 24 + (gc << 2)) = ul;
        }
        __syncthreads();

        // ---- A fragments: 2 p-tiles x (hi,lo) ----
        unsigned ah[2][4], al[2][4];
#pragma unroll
        for (int pt = 0; pt < 2; ++pt) {
            int prow = (pw << 5) + (pt << 4) + a_row_off;
            unsigned addr_h = smem_u32(s_sm[0] + prow * 24 + a_col_off);
            unsigned addr_l = smem_u32(s_sm[1] + prow * 24 + a_col_off);
            asm volatile("ldmatrix.sync.aligned.m8n8.x4.shared.b16 {%0,%1,%2,%3}, [%4];"
                : "=r"(ah[pt][0]), "=r"(ah[pt][1]), "=r"(ah[pt][2]), "=r"(ah[pt][3])
                : "r"(addr_h));
            asm volatile("ldmatrix.sync.aligned.m8n8.x4.shared.b16 {%0,%1,%2,%3}, [%4];"
                : "=r"(al[pt][0]), "=r"(al[pt][1]), "=r"(al[pt][2]), "=r"(al[pt][3])
                : "r"(addr_l));
        }

        // ---- B fragments + mma: 4 x4-loads cover 8 o-tiles per split ----
#pragma unroll
        for (int otp = 0; otp < 4; ++otp) {
            int orow = (ow << 6) + (otp << 4) + b_row_off;
            unsigned addr_h = smem_u32(w_sm[0] + orow * 24 + b_col_off);
            unsigned addr_l = smem_u32(w_sm[1] + orow * 24 + b_col_off);
            unsigned bh[4], bl[4];
            asm volatile("ldmatrix.sync.aligned.m8n8.x4.shared.b16 {%0,%1,%2,%3}, [%4];"
                : "=r"(bh[0]), "=r"(bh[1]), "=r"(bh[2]), "=r"(bh[3]) : "r"(addr_h));
            asm volatile("ldmatrix.sync.aligned.m8n8.x4.shared.b16 {%0,%1,%2,%3}, [%4];"
                : "=r"(bl[0]), "=r"(bl[1]), "=r"(bl[2]), "=r"(bl[3]) : "r"(addr_l));
#pragma unroll
            for (int sub = 0; sub < 2; ++sub) {
                int ot = (otp << 1) + sub;
#pragma unroll
                for (int pt = 0; pt < 2; ++pt) {
                    float* d = acc[pt][ot];
#define MMA(A, B0, B1) \
    asm volatile("mma.sync.aligned.m16n8k16.row.col.f32.bf16.bf16.f32 " \
        "{%0,%1,%2,%3},{%4,%5,%6,%7},{%8,%9},{%0,%1,%2,%3};" \
        : "+f"(d[0]), "+f"(d[1]), "+f"(d[2]), "+f"(d[3]) \
        : "r"(A[0]), "r"(A[1]), "r"(A[2]), "r"(A[3]), "r"(B0), "r"(B1))
                    MMA(ah[pt], bh[sub * 2], bh[sub * 2 + 1]);
                    MMA(al[pt], bh[sub * 2], bh[sub * 2 + 1]);
                    MMA(ah[pt], bl[sub * 2], bl[sub * 2 + 1]);
#undef MMA
                }
            }
        }
        __syncthreads();
    }

    // ---- epilogue: bias + scattered fp32 stores ----
    const long ob_base = ((long)b << 8);
#pragma unroll
    for (int ot = 0; ot < 8; ++ot) {
        int oc = (ow << 6) + (ot << 3) + ((lane & 3) << 1);
        float b0 = __ldg(&bias[oc]);
        float b1 = __ldg(&bias[oc + 1]);
        float* o0p = out + ((ob_base + oc) << 12) + (y << 6);
        float* o1p = out + ((ob_base + oc + 1) << 12) + (y << 6);
#pragma unroll
        for (int pt = 0; pt < 2; ++pt) {
            const float* d = acc[pt][ot];
            int r0 = (pw << 5) + (pt << 4) + (lane >> 2);
            int r1 = r0 + 8;
            o0p[r0] = d[0] + b0;
            o1p[r0] = d[1] + b1;
            o0p[r1] = d[2] + b0;
            o1p[r1] = d[3] + b1;
        }
    }
}

// ---------------------------------------------------------------------------
// Launch: inputs per metadata order: input, coord_offset, coord_weight, weight, bias
// ---------------------------------------------------------------------------
extern "C" void kernel_launch(void* const* d_in, const int* in_sizes, int n_in,
                              void* d_out, int out_size) {
    const float* x    = (const float*)d_in[0];
    const float* coff = (const float*)d_in[1];
    const float* cwt  = (const float*)d_in[2];
    const float* wt   = (const float*)d_in[3];
    const float* bias = (const float*)d_in[4];
    float* out = (float*)d_out;

    dcn_split_w<<<(KK_ * O_ * C_ + 255) / 256, 256>>>(wt);
    dcn_main<<<B_ * H_, 256>>>(x, coff, cwt, bias, out);
}

// round 12
// speedup vs baseline: 2.0116x; 1.5194x over previous
#include <cuda_runtime.h>
#include <cuda_bf16.h>

// Problem constants
#define B_  8
#define C_  256
#define O_  256
#define H_  64
#define W_  64
#define HW_ 4096
#define KK_ 9

// Static scratch: weights pre-split (bf16 hi/lo) AND pre-staged in the exact
// per-stage smem tile layout: [kk][chunk16][split][o][24elem-padded-row].
// => per-stage staging is a flat coalesced memcpy. 3.4 MiB total.
#define WROW_ 24
__device__ __nv_bfloat16 g_ws[KK_ * 16 * 2 * O_ * WROW_];

__device__ __forceinline__ unsigned smem_u32(const void* p) {
    unsigned r;
    asm("{ .reg .u64 t; cvta.to.shared.u64 t, %1; cvt.u32.u64 %0, t; }"
        : "=r"(r) : "l"(p));
    return r;
}
__device__ __forceinline__ unsigned pkbf(__nv_bfloat16 a, __nv_bfloat16 b) {
    return (unsigned)__bfloat16_as_ushort(a) |
           ((unsigned)__bfloat16_as_ushort(b) << 16);
}

// ---------------------------------------------------------------------------
// Kernel 1: weight (O,C,3,3) fp32 -> staged bf16 hi/lo tiles (pad = 0)
// ---------------------------------------------------------------------------
__global__ void dcn_split_w(const float* __restrict__ w) {
    int i = blockIdx.x * 256 + threadIdx.x;
    if (i >= KK_ * 16 * 2 * O_ * WROW_) return;
    int e     = i % WROW_;
    int o     = (i / WROW_) & 255;
    int split = (i / (WROW_ * 256)) & 1;
    int chunk = (i / (WROW_ * 512)) & 15;
    int kk    = i / (WROW_ * 512 * 16);
    __nv_bfloat16 val = __float2bfloat16_rn(0.0f);
    if (e < 16) {
        int c = (chunk << 4) + e;
        float v = w[o * 2304 + c * 9 + kk];
        __nv_bfloat16 hi = __float2bfloat16_rn(v);
        val = split == 0 ? hi
                         : __float2bfloat16_rn(v - __bfloat162float(hi));
    }
    g_ws[i] = val;
}

// ---------------------------------------------------------------------------
// Kernel 2: fused bilinear-im2col + bf16 tensor-core GEMM (3-term split).
// CTA: one image row (64 p) x 256 o.  144 stages = 9 taps x 16 c-chunks of 16.
// Per stage: flat-copy staged w tile (coalesced LDG.128 -> linear STS.128),
// gather s [64p][16c] hi/lo, then each warp: 12 ldmatrix.x4 + 48 mma.sync
// m16n8k16 (D += Ah*Bh + Al*Bh + Ah*Bl). 24-elem rows: conflict-free ldmatrix.
// ---------------------------------------------------------------------------
__global__ __launch_bounds__(256, 2)
void dcn_main(const float* __restrict__ x,      // (B, C, H, W)
              const float* __restrict__ coff,   // (B, 2*KK, H, W)
              const float* __restrict__ cwt,    // (B, KK, H, W)
              const float* __restrict__ bias,   // (O)
              float* __restrict__ out)          // (B, O, H, W)
{
    __shared__ __nv_bfloat16 w_sm[2][256 * WROW_]; // [split][o][24] 24576 B
    __shared__ __nv_bfloat16 s_sm[2][64 * WROW_];  // [split][p][24]  6144 B
    __shared__ float pwgt[KK_ * 4 * 64];           //                 9216 B
    __shared__ int   pspat[KK_ * 2 * 64];          // packed pairs    4608 B

    const int cta = blockIdx.x;        // 512 CTAs
    const int b   = cta >> 6;
    const int y   = cta & 63;

    const int tid  = threadIdx.x;
    const int wrp  = tid >> 5;
    const int lane = tid & 31;
    const int ow   = wrp & 3;          // o-group: o_base = ow*64
    const int pw   = wrp >> 2;         // p-group: p_base = pw*32

    const float* xbb = x + ((long)b << 20);

    // ---- one-time prep: all taps' corner indices + folded weights ----
    for (int i = tid; i < KK_ * 64; i += 256) {
        int kk = i >> 6;
        int pp = i & 63;
        int base_oy = ((b * 18 + 2 * kk) * 64 + y) * 64 + pp;
        float oy = __ldg(&coff[base_oy]);
        float ox = __ldg(&coff[base_oy + HW_]);
        float cw = __ldg(&cwt[((b * 9 + kk) * 64 + y) * 64 + pp]);
        int ky = kk / 3;
        int kx = kk - ky * 3;
        float py = (float)(y  - 1 + ky) + oy;
        float px = (float)(pp - 1 + kx) + ox;
        float fy = floorf(py), fx = floorf(px);
        int   y0 = (int)fy,    x0 = (int)fx;
        float wy1 = py - fy, wy0 = 1.0f - wy1;
        float wx1 = px - fx, wx0 = 1.0f - wx1;
        bool vy0 = (y0 >= 0)  && (y0 < H_);
        bool vy1 = (y0 >= -1) && (y0 < H_ - 1);
        bool vx0 = (x0 >= 0)  && (x0 < W_);
        bool vx1 = (x0 >= -1) && (x0 < W_ - 1);
        int yc0 = max(0, min(H_ - 1, y0));
        int yc1 = max(0, min(H_ - 1, y0 + 1));
        int xc0 = max(0, min(W_ - 1, x0));
        int xc1 = max(0, min(W_ - 1, x0 + 1));
        int s0 = (yc0 << 6) + xc0, s1 = (yc0 << 6) + xc1;
        int s2 = (yc1 << 6) + xc0, s3 = (yc1 << 6) + xc1;
        pspat[(kk << 7) + pp]      = s0 | (s1 << 16);
        pspat[(kk << 7) + 64 + pp] = s2 | (s3 << 16);
        pwgt[(kk << 8) + pp]        = (vy0 && vx0) ? cw * wy0 * wx0 : 0.0f;
        pwgt[(kk << 8) + 64 + pp]   = (vy0 && vx1) ? cw * wy0 * wx1 : 0.0f;
        pwgt[(kk << 8) + 128 + pp]  = (vy1 && vx0) ? cw * wy1 * wx0 : 0.0f;
        pwgt[(kk << 8) + 192 + pp]  = (vy1 && vx1) ? cw * wy1 * wx1 : 0.0f;
    }
    __syncthreads();

    float acc[2][8][4];                // [p-tile][o-tile][frag]
#pragma unroll
    for (int i = 0; i < 2; ++i)
#pragma unroll
        for (int j = 0; j < 8; ++j)
#pragma unroll
            for (int k = 0; k < 4; ++k) acc[i][j][k] = 0.0f;

    // gather role: low 6 bits = position, high bits = c sub-group
    const int gp = tid & 63;           // position 0..63
    const int gc = tid >> 6;           // c sub-group 0..3 (4 c's each)

    // ldmatrix lane address offsets
    const int a_row_off = (lane & 15);
    const int a_col_off = (lane >> 4) << 3;
    const int b_row_off = ((lane >> 4) << 3) + (lane & 7);
    const int b_col_off = ((lane >> 3) & 1) << 3;

    for (int s = 0; s < 144; ++s) {
        const int kk = s >> 4;
        const int c0 = (s & 15) << 4;

        // ---- stage weights: FLAT memcpy of pre-staged tile (24576 B) ----
        {
            const uint4* src = (const uint4*)
                (g_ws + (((kk << 4) + (s & 15)) << 1) * (256 * WROW_));
            uint4* dst = (uint4*)w_sm;
#pragma unroll
            for (int i = 0; i < 6; ++i)
                dst[tid + (i << 8)] = src[tid + (i << 8)];
        }

        // ---- gather s tile: thread -> (p=gp, c = c0+gc*4 .. +3) ----
        {
            int pk01 = pspat[(kk << 7) + gp];
            int pk23 = pspat[(kk << 7) + 64 + gp];
            int sp0 = pk01 & 0xFFFF, sp1 = ((unsigned)pk01) >> 16;
            int sp2 = pk23 & 0xFFFF, sp3 = ((unsigned)pk23) >> 16;
            float g0 = pwgt[(kk << 8) + gp];
            float g1 = pwgt[(kk << 8) + 64 + gp];
            float g2 = pwgt[(kk << 8) + 128 + gp];
            float g3 = pwgt[(kk << 8) + 192 + gp];
            __nv_bfloat16 hv[4], lv[4];
#pragma unroll
            for (int j = 0; j < 4; ++j) {
                const float* pl = xbb + ((c0 + (gc << 2) + j) << 12);
                float v = g0 * __ldg(pl + sp0) + g1 * __ldg(pl + sp1)
                        + g2 * __ldg(pl + sp2) + g3 * __ldg(pl + sp3);
                hv[j] = __float2bfloat16_rn(v);
                lv[j] = __float2bfloat16_rn(v - __bfloat162float(hv[j]));
            }
            uint2 uh = make_uint2(pkbf(hv[0], hv[1]), pkbf(hv[2], hv[3]));
            uint2 ul = make_uint2(pkbf(lv[0], lv[1]), pkbf(lv[2], lv[3]));
            *(uint2*)(s_sm[0] + gp * WROW_ + (gc << 2)) = uh;
            *(uint2*)(s_sm[1] + gp * WROW_ + (gc << 2)) = ul;
        }
        __syncthreads();

        // ---- A fragments: 2 p-tiles x (hi,lo) ----
        unsigned ah[2][4], al[2][4];
#pragma unroll
        for (int pt = 0; pt < 2; ++pt) {
            int prow = (pw << 5) + (pt << 4) + a_row_off;
            unsigned addr_h = smem_u32(s_sm[0] + prow * WROW_ + a_col_off);
            unsigned addr_l = smem_u32(s_sm[1] + prow * WROW_ + a_col_off);
            asm volatile("ldmatrix.sync.aligned.m8n8.x4.shared.b16 {%0,%1,%2,%3}, [%4];"
                : "=r"(ah[pt][0]), "=r"(ah[pt][1]), "=r"(ah[pt][2]), "=r"(ah[pt][3])
                : "r"(addr_h));
            asm volatile("ldmatrix.sync.aligned.m8n8.x4.shared.b16 {%0,%1,%2,%3}, [%4];"
                : "=r"(al[pt][0]), "=r"(al[pt][1]), "=r"(al[pt][2]), "=r"(al[pt][3])
                : "r"(addr_l));
        }

        // ---- B fragments + mma: 4 x4-loads cover 8 o-tiles per split ----
#pragma unroll
        for (int otp = 0; otp < 4; ++otp) {
            int orow = (ow << 6) + (otp << 4) + b_row_off;
            unsigned addr_h = smem_u32(w_sm[0] + orow * WROW_ + b_col_off);
            unsigned addr_l = smem_u32(w_sm[1] + orow * WROW_ + b_col_off);
            unsigned bh[4], bl[4];
            asm volatile("ldmatrix.sync.aligned.m8n8.x4.shared.b16 {%0,%1,%2,%3}, [%4];"
                : "=r"(bh[0]), "=r"(bh[1]), "=r"(bh[2]), "=r"(bh[3]) : "r"(addr_h));
            asm volatile("ldmatrix.sync.aligned.m8n8.x4.shared.b16 {%0,%1,%2,%3}, [%4];"
                : "=r"(bl[0]), "=r"(bl[1]), "=r"(bl[2]), "=r"(bl[3]) : "r"(addr_l));
#pragma unroll
            for (int sub = 0; sub < 2; ++sub) {
                int ot = (otp << 1) + sub;
#pragma unroll
                for (int pt = 0; pt < 2; ++pt) {
                    float* d = acc[pt][ot];
#define MMA(A, B0, B1) \
    asm volatile("mma.sync.aligned.m16n8k16.row.col.f32.bf16.bf16.f32 " \
        "{%0,%1,%2,%3},{%4,%5,%6,%7},{%8,%9},{%0,%1,%2,%3};" \
        : "+f"(d[0]), "+f"(d[1]), "+f"(d[2]), "+f"(d[3]) \
        : "r"(A[0]), "r"(A[1]), "r"(A[2]), "r"(A[3]), "r"(B0), "r"(B1))
                    MMA(ah[pt], bh[sub * 2], bh[sub * 2 + 1]);
                    MMA(al[pt], bh[sub * 2], bh[sub * 2 + 1]);
                    MMA(ah[pt], bl[sub * 2], bl[sub * 2 + 1]);
#undef MMA
                }
            }
        }
        __syncthreads();
    }

    // ---- epilogue: bias + fp32 stores ----
    const long ob_base = ((long)b << 8);
#pragma unroll
    for (int ot = 0; ot < 8; ++ot) {
        int oc = (ow << 6) + (ot << 3) + ((lane & 3) << 1);
        float b0 = __ldg(&bias[oc]);
        float b1 = __ldg(&bias[oc + 1]);
        float* o0p = out + ((ob_base + oc) << 12) + (y << 6);
        float* o1p = out + ((ob_base + oc + 1) << 12) + (y << 6);
#pragma unroll
        for (int pt = 0; pt < 2; ++pt) {
            const float* d = acc[pt][ot];
            int r0 = (pw << 5) + (pt << 4) + (lane >> 2);
            int r1 = r0 + 8;
            o0p[r0] = d[0] + b0;
            o1p[r0] = d[1] + b1;
            o0p[r1] = d[2] + b0;
            o1p[r1] = d[3] + b1;
        }
    }
}

// ---------------------------------------------------------------------------
// Launch: inputs per metadata order: input, coord_offset, coord_weight, weight, bias
// ---------------------------------------------------------------------------
extern "C" void kernel_launch(void* const* d_in, const int* in_sizes, int n_in,
                              void* d_out, int out_size) {
    const float* x    = (const float*)d_in[0];
    const float* coff = (const float*)d_in[1];
    const float* cwt  = (const float*)d_in[2];
    const float* wt   = (const float*)d_in[3];
    const float* bias = (const float*)d_in[4];
    float* out = (float*)d_out;

    int n_ws = KK_ * 16 * 2 * O_ * WROW_;
    dcn_split_w<<<(n_ws + 255) / 256, 256>>>(wt);
    dcn_main<<<B_ * H_, 256>>>(x, coff, cwt, bias, out);
}

// round 13
// speedup vs baseline: 2.3487x; 1.1676x over previous
#include <cuda_runtime.h>
#include <cuda_bf16.h>

// Problem constants
#define B_  8
#define C_  256
#define O_  256
#define H_  64
#define W_  64
#define HW_ 4096
#define KK_ 9
#define WROW_ 24

// Static scratch: weights pre-split (bf16 hi/lo) pre-staged in the exact smem
// tile layout [kk][chunk16][split][o][24-padded]. 3.4 MiB.
__device__ __nv_bfloat16 g_ws[KK_ * 16 * 2 * O_ * WROW_];

// dynamic smem layout (bytes)
#define SM_W    0                      // w tiles: 2 bufs x 2 splits x 256 x 24 x 2B = 49152
#define SM_S    49152                  // s tiles: 2 bufs x 2 splits x 64 x 24 x 2B  = 12288
#define SM_PW   61440                  // pwgt: 9*4*64 floats                        =  9216
#define SM_PS   70656                  // pspat: 9*2*64 ints                         =  4608
#define SM_TOT  75264
#define W_BUF   12288                  // elems per w buffer
#define W_SPL   6144
#define S_BUF   3072                   // elems per s buffer
#define S_SPL   1536

__device__ __forceinline__ unsigned smem_u32(const void* p) {
    unsigned r;
    asm("{ .reg .u64 t; cvta.to.shared.u64 t, %1; cvt.u32.u64 %0, t; }"
        : "=r"(r) : "l"(p));
    return r;
}
__device__ __forceinline__ unsigned pkbf(__nv_bfloat16 a, __nv_bfloat16 b) {
    return (unsigned)__bfloat16_as_ushort(a) |
           ((unsigned)__bfloat16_as_ushort(b) << 16);
}
__device__ __forceinline__ void cpasync16(unsigned dst, const void* src) {
    asm volatile("cp.async.ca.shared.global [%0], [%1], 16;"
                 :: "r"(dst), "l"(src));
}

// ---------------------------------------------------------------------------
// Kernel 1: weight (O,C,3,3) fp32 -> staged bf16 hi/lo tiles (pad = 0)
// ---------------------------------------------------------------------------
__global__ void dcn_split_w(const float* __restrict__ w) {
    int i = blockIdx.x * 256 + threadIdx.x;
    if (i >= KK_ * 16 * 2 * O_ * WROW_) return;
    int e     = i % WROW_;
    int o     = (i / WROW_) & 255;
    int split = (i / (WROW_ * 256)) & 1;
    int chunk = (i / (WROW_ * 512)) & 15;
    int kk    = i / (WROW_ * 512 * 16);
    __nv_bfloat16 val = __float2bfloat16_rn(0.0f);
    if (e < 16) {
        int c = (chunk << 4) + e;
        float v = w[o * 2304 + c * 9 + kk];
        __nv_bfloat16 hi = __float2bfloat16_rn(v);
        val = split == 0 ? hi
                         : __float2bfloat16_rn(v - __bfloat162float(hi));
    }
    g_ws[i] = val;
}

// ---------------------------------------------------------------------------
// Kernel 2: fused bilinear-im2col + bf16 tensor-core GEMM (3-term split),
// single-barrier pipelined: per stage -> cp.async-prefetch w(s+1),
// ldmatrix+mma(s), gather s(s+1), wait+barrier. Both tiles double-buffered.
// ---------------------------------------------------------------------------
__global__ __launch_bounds__(256, 2)
void dcn_main(const float* __restrict__ x,      // (B, C, H, W)
              const float* __restrict__ coff,   // (B, 2*KK, H, W)
              const float* __restrict__ cwt,    // (B, KK, H, W)
              const float* __restrict__ bias,   // (O)
              float* __restrict__ out)          // (B, O, H, W)
{
    extern __shared__ char smem_raw[];
    __nv_bfloat16* w_sm = (__nv_bfloat16*)(smem_raw + SM_W);
    __nv_bfloat16* s_sm = (__nv_bfloat16*)(smem_raw + SM_S);
    float*         pwgt = (float*)(smem_raw + SM_PW);
    int*           pspat = (int*)(smem_raw + SM_PS);

    const int cta = blockIdx.x;        // 512 CTAs
    const int b   = cta >> 6;
    const int y   = cta & 63;

    const int tid  = threadIdx.x;
    const int wrp  = tid >> 5;
    const int lane = tid & 31;
    const int ow   = wrp & 3;          // o-group: o_base = ow*64
    const int pw   = wrp >> 2;         // p-group: p_base = pw*32

    const float* xbb = x + ((long)b << 20);

    // ---- one-time prep: all taps' corner indices + folded weights ----
    for (int i = tid; i < KK_ * 64; i += 256) {
        int kk = i >> 6;
        int pp = i & 63;
        int base_oy = ((b * 18 + 2 * kk) * 64 + y) * 64 + pp;
        float oy = __ldg(&coff[base_oy]);
        float ox = __ldg(&coff[base_oy + HW_]);
        float cw = __ldg(&cwt[((b * 9 + kk) * 64 + y) * 64 + pp]);
        int ky = kk / 3;
        int kx = kk - ky * 3;
        float py = (float)(y  - 1 + ky) + oy;
        float px = (float)(pp - 1 + kx) + ox;
        float fy = floorf(py), fx = floorf(px);
        int   y0 = (int)fy,    x0 = (int)fx;
        float wy1 = py - fy, wy0 = 1.0f - wy1;
        float wx1 = px - fx, wx0 = 1.0f - wx1;
        bool vy0 = (y0 >= 0)  && (y0 < H_);
        bool vy1 = (y0 >= -1) && (y0 < H_ - 1);
        bool vx0 = (x0 >= 0)  && (x0 < W_);
        bool vx1 = (x0 >= -1) && (x0 < W_ - 1);
        int yc0 = max(0, min(H_ - 1, y0));
        int yc1 = max(0, min(H_ - 1, y0 + 1));
        int xc0 = max(0, min(W_ - 1, x0));
        int xc1 = max(0, min(W_ - 1, x0 + 1));
        int s0 = (yc0 << 6) + xc0, s1 = (yc0 << 6) + xc1;
        int s2 = (yc1 << 6) + xc0, s3 = (yc1 << 6) + xc1;
        pspat[(kk << 7) + pp]      = s0 | (s1 << 16);
        pspat[(kk << 7) + 64 + pp] = s2 | (s3 << 16);
        pwgt[(kk << 8) + pp]        = (vy0 && vx0) ? cw * wy0 * wx0 : 0.0f;
        pwgt[(kk << 8) + 64 + pp]   = (vy0 && vx1) ? cw * wy0 * wx1 : 0.0f;
        pwgt[(kk << 8) + 128 + pp]  = (vy1 && vx0) ? cw * wy1 * wx0 : 0.0f;
        pwgt[(kk << 8) + 192 + pp]  = (vy1 && vx1) ? cw * wy1 * wx1 : 0.0f;
    }
    __syncthreads();

    float acc[2][8][4];
#pragma unroll
    for (int i = 0; i < 2; ++i)
#pragma unroll
        for (int j = 0; j < 8; ++j)
#pragma unroll
            for (int k = 0; k < 4; ++k) acc[i][j][k] = 0.0f;

    // gather role
    const int gp = tid & 63;           // position 0..63
    const int gc = tid >> 6;           // c sub-group 0..3

    // ldmatrix lane address offsets
    const int a_row_off = (lane & 15);
    const int a_col_off = (lane >> 4) << 3;
    const int b_row_off = ((lane >> 4) << 3) + (lane & 7);
    const int b_col_off = ((lane >> 3) & 1) << 3;

    const unsigned w_sm_base = smem_u32(w_sm);

    // ---- helpers as lambdas ----
    auto prefetch_w = [&](int t) {
        const char* src = (const char*)(g_ws + (((t >> 4) << 4) + (t & 15)) * 2 * (256 * WROW_));
        unsigned dst = w_sm_base + (unsigned)((t & 1) * W_BUF * 2);
#pragma unroll
        for (int i = 0; i < 6; ++i)
            cpasync16(dst + ((tid + (i << 8)) << 4),
                      src + ((tid + (i << 8)) << 4));
        asm volatile("cp.async.commit_group;");
    };
    auto gather_s = [&](int t) {
        int kk = t >> 4;
        int c0 = (t & 15) << 4;
        int pk01 = pspat[(kk << 7) + gp];
        int pk23 = pspat[(kk << 7) + 64 + gp];
        int sp0 = pk01 & 0xFFFF, sp1 = ((unsigned)pk01) >> 16;
        int sp2 = pk23 & 0xFFFF, sp3 = ((unsigned)pk23) >> 16;
        float g0 = pwgt[(kk << 8) + gp];
        float g1 = pwgt[(kk << 8) + 64 + gp];
        float g2 = pwgt[(kk << 8) + 128 + gp];
        float g3 = pwgt[(kk << 8) + 192 + gp];
        __nv_bfloat16 hv[4], lv[4];
#pragma unroll
        for (int j = 0; j < 4; ++j) {
            const float* pl = xbb + ((c0 + (gc << 2) + j) << 12);
            float v = g0 * __ldg(pl + sp0) + g1 * __ldg(pl + sp1)
                    + g2 * __ldg(pl + sp2) + g3 * __ldg(pl + sp3);
            hv[j] = __float2bfloat16_rn(v);
            lv[j] = __float2bfloat16_rn(v - __bfloat162float(hv[j]));
        }
        __nv_bfloat16* sb = s_sm + (t & 1) * S_BUF;
        *(uint2*)(sb + gp * WROW_ + (gc << 2)) =
            make_uint2(pkbf(hv[0], hv[1]), pkbf(hv[2], hv[3]));
        *(uint2*)(sb + S_SPL + gp * WROW_ + (gc << 2)) =
            make_uint2(pkbf(lv[0], lv[1]), pkbf(lv[2], lv[3]));
    };

    // ---- prologue: stage-0 tiles ----
    prefetch_w(0);
    gather_s(0);
    asm volatile("cp.async.wait_group 0;");
    __syncthreads();

    // ---- 144 single-barrier pipelined stages ----
    for (int s = 0; s < 144; ++s) {
        if (s < 143) prefetch_w(s + 1);

        const __nv_bfloat16* sb = s_sm + (s & 1) * S_BUF;
        const __nv_bfloat16* wb = w_sm + (s & 1) * W_BUF;

        // A fragments: 2 p-tiles x (hi,lo)
        unsigned ah[2][4], al[2][4];
#pragma unroll
        for (int pt = 0; pt < 2; ++pt) {
            int prow = (pw << 5) + (pt << 4) + a_row_off;
            unsigned addr_h = smem_u32(sb + prow * WROW_ + a_col_off);
            unsigned addr_l = smem_u32(sb + S_SPL + prow * WROW_ + a_col_off);
            asm volatile("ldmatrix.sync.aligned.m8n8.x4.shared.b16 {%0,%1,%2,%3}, [%4];"
                : "=r"(ah[pt][0]), "=r"(ah[pt][1]), "=r"(ah[pt][2]), "=r"(ah[pt][3])
                : "r"(addr_h));
            asm volatile("ldmatrix.sync.aligned.m8n8.x4.shared.b16 {%0,%1,%2,%3}, [%4];"
                : "=r"(al[pt][0]), "=r"(al[pt][1]), "=r"(al[pt][2]), "=r"(al[pt][3])
                : "r"(addr_l));
        }

        // B fragments + mma
#pragma unroll
        for (int otp = 0; otp < 4; ++otp) {
            int orow = (ow << 6) + (otp << 4) + b_row_off;
            unsigned addr_h = smem_u32(wb + orow * WROW_ + b_col_off);
            unsigned addr_l = smem_u32(wb + W_SPL + orow * WROW_ + b_col_off);
            unsigned bh[4], bl[4];
            asm volatile("ldmatrix.sync.aligned.m8n8.x4.shared.b16 {%0,%1,%2,%3}, [%4];"
                : "=r"(bh[0]), "=r"(bh[1]), "=r"(bh[2]), "=r"(bh[3]) : "r"(addr_h));
            asm volatile("ldmatrix.sync.aligned.m8n8.x4.shared.b16 {%0,%1,%2,%3}, [%4];"
                : "=r"(bl[0]), "=r"(bl[1]), "=r"(bl[2]), "=r"(bl[3]) : "r"(addr_l));
#pragma unroll
            for (int sub = 0; sub < 2; ++sub) {
                int ot = (otp << 1) + sub;
#pragma unroll
                for (int pt = 0; pt < 2; ++pt) {
                    float* d = acc[pt][ot];
#define MMA(A, B0, B1) \
    asm volatile("mma.sync.aligned.m16n8k16.row.col.f32.bf16.bf16.f32 " \
        "{%0,%1,%2,%3},{%4,%5,%6,%7},{%8,%9},{%0,%1,%2,%3};" \
        : "+f"(d[0]), "+f"(d[1]), "+f"(d[2]), "+f"(d[3]) \
        : "r"(A[0]), "r"(A[1]), "r"(A[2]), "r"(A[3]), "r"(B0), "r"(B1))
                    MMA(ah[pt], bh[sub * 2], bh[sub * 2 + 1]);
                    MMA(al[pt], bh[sub * 2], bh[sub * 2 + 1]);
                    MMA(ah[pt], bl[sub * 2], bl[sub * 2 + 1]);
#undef MMA
                }
            }
        }

        if (s < 143) gather_s(s + 1);
        asm volatile("cp.async.wait_group 0;");
        __syncthreads();
    }

    // ---- epilogue: bias + fp32 stores ----
    const long ob_base = ((long)b << 8);
#pragma unroll
    for (int ot = 0; ot < 8; ++ot) {
        int oc = (ow << 6) + (ot << 3) + ((lane & 3) << 1);
        float b0 = __ldg(&bias[oc]);
        float b1 = __ldg(&bias[oc + 1]);
        float* o0p = out + ((ob_base + oc) << 12) + (y << 6);
        float* o1p = out + ((ob_base + oc + 1) << 12) + (y << 6);
#pragma unroll
        for (int pt = 0; pt < 2; ++pt) {
            const float* d = acc[pt][ot];
            int r0 = (pw << 5) + (pt << 4) + (lane >> 2);
            int r1 = r0 + 8;
            o0p[r0] = d[0] + b0;
            o1p[r0] = d[1] + b1;
            o0p[r1] = d[2] + b0;
            o1p[r1] = d[3] + b1;
        }
    }
}

// ---------------------------------------------------------------------------
// Launch: inputs per metadata order: input, coord_offset, coord_weight, weight, bias
// ---------------------------------------------------------------------------
extern "C" void kernel_launch(void* const* d_in, const int* in_sizes, int n_in,
                              void* d_out, int out_size) {
    const float* x    = (const float*)d_in[0];
    const float* coff = (const float*)d_in[1];
    const float* cwt  = (const float*)d_in[2];
    const float* wt   = (const float*)d_in[3];
    const float* bias = (const float*)d_in[4];
    float* out = (float*)d_out;

    static int smem_set = 0;
    if (!smem_set) {
        cudaFuncSetAttribute(dcn_main,
                             cudaFuncAttributeMaxDynamicSharedMemorySize,
                             SM_TOT);
        smem_set = 1;
    }

    int n_ws = KK_ * 16 * 2 * O_ * WROW_;
    dcn_split_w<<<(n_ws + 255) / 256, 256>>>(wt);
    dcn_main<<<B_ * H_, 256, SM_TOT>>>(x, coff, cwt, bias, out);
}

// round 14
// speedup vs baseline: 2.5129x; 1.0699x over previous
#include <cuda_runtime.h>
#include <cuda_bf16.h>

// Problem constants
#define B_  8
#define C_  256
#define O_  256
#define H_  64
#define W_  64
#define HW_ 4096
#define KK_ 9
#define WROW_ 24

// Static scratch: weights pre-split (bf16 hi/lo) pre-staged in the exact smem
// tile layout [kk][chunk16][split][o][24-padded]. 3.4 MiB.
__device__ __nv_bfloat16 g_ws[KK_ * 16 * 2 * O_ * WROW_];

// dynamic smem layout (bytes)
#define SM_W    0                      // w tiles: 2 bufs x 2 spl x 256 x 24 x 2B = 49152
#define SM_S    49152                  // s tiles: 2 bufs x 2 spl x 64 x 24 x 2B  = 12288
#define SM_PW   61440                  // pwgt: 9*4*64 floats                     =  9216
#define SM_PS   70656                  // pspat: 9*2*64 ints                      =  4608
#define SM_MB   75264                  // mbarrier (8B)
#define SM_TOT  75280
#define W_BUF   12288                  // elems per w buffer
#define W_SPL   6144
#define S_BUF   3072                   // elems per s buffer
#define S_SPL   1536
#define W_TILE_BYTES 24576

__device__ __forceinline__ unsigned smem_u32(const void* p) {
    unsigned r;
    asm("{ .reg .u64 t; cvta.to.shared.u64 t, %1; cvt.u32.u64 %0, t; }"
        : "=r"(r) : "l"(p));
    return r;
}
__device__ __forceinline__ unsigned pkbf(__nv_bfloat16 a, __nv_bfloat16 b) {
    return (unsigned)__bfloat16_as_ushort(a) |
           ((unsigned)__bfloat16_as_ushort(b) << 16);
}
__device__ __forceinline__ void mbar_init(unsigned mbar, unsigned cnt) {
    asm volatile("mbarrier.init.shared.b64 [%0], %1;" :: "r"(mbar), "r"(cnt) : "memory");
}
__device__ __forceinline__ void mbar_expect_tx(unsigned mbar, unsigned bytes) {
    asm volatile("mbarrier.arrive.expect_tx.shared.b64 _, [%0], %1;"
                 :: "r"(mbar), "r"(bytes) : "memory");
}
__device__ __forceinline__ void mbar_wait(unsigned mbar, unsigned parity) {
    asm volatile(
        "{\n\t"
        ".reg .pred P;\n\t"
        "WL_%=:\n\t"
        "mbarrier.try_wait.parity.shared.b64 P, [%0], %1;\n\t"
        "@P bra.uni WD_%=;\n\t"
        "bra.uni WL_%=;\n\t"
        "WD_%=:\n\t"
        "}"
        :: "r"(mbar), "r"(parity) : "memory");
}
__device__ __forceinline__ void bulk_copy(unsigned dst, const void* src,
                                          unsigned bytes, unsigned mbar) {
    asm volatile(
        "cp.async.bulk.shared::cta.global.mbarrier::complete_tx::bytes "
        "[%0], [%1], %2, [%3];"
        :: "r"(dst), "l"(src), "r"(bytes), "r"(mbar) : "memory");
}

// ---------------------------------------------------------------------------
// Kernel 1: weight (O,C,3,3) fp32 -> staged bf16 hi/lo tiles (pad = 0)
// ---------------------------------------------------------------------------
__global__ void dcn_split_w(const float* __restrict__ w) {
    int i = blockIdx.x * 256 + threadIdx.x;
    if (i >= KK_ * 16 * 2 * O_ * WROW_) return;
    int e     = i % WROW_;
    int o     = (i / WROW_) & 255;
    int split = (i / (WROW_ * 256)) & 1;
    int chunk = (i / (WROW_ * 512)) & 15;
    int kk    = i / (WROW_ * 512 * 16);
    __nv_bfloat16 val = __float2bfloat16_rn(0.0f);
    if (e < 16) {
        int c = (chunk << 4) + e;
        float v = w[o * 2304 + c * 9 + kk];
        __nv_bfloat16 hi = __float2bfloat16_rn(v);
        val = split == 0 ? hi
                         : __float2bfloat16_rn(v - __bfloat162float(hi));
    }
    g_ws[i] = val;
}

// ---------------------------------------------------------------------------
// Kernel 2: fused bilinear-im2col + bf16 tensor-core GEMM (3-term split).
// Per stage: ONE cp.async.bulk (UBLKCP) prefetches w(s+1) via mbarrier;
// gather LDGs for s(s+1) hoisted above/between the mma halves; single
// __syncthreads per stage. Both tiles double-buffered.
// ---------------------------------------------------------------------------
__global__ __launch_bounds__(256, 2)
void dcn_main(const float* __restrict__ x,      // (B, C, H, W)
              const float* __restrict__ coff,   // (B, 2*KK, H, W)
              const float* __restrict__ cwt,    // (B, KK, H, W)
              const float* __restrict__ bias,   // (O)
              float* __restrict__ out)          // (B, O, H, W)
{
    extern __shared__ char smem_raw[];
    __nv_bfloat16* w_sm = (__nv_bfloat16*)(smem_raw + SM_W);
    __nv_bfloat16* s_sm = (__nv_bfloat16*)(smem_raw + SM_S);
    float*         pwgt = (float*)(smem_raw + SM_PW);
    int*           pspat = (int*)(smem_raw + SM_PS);
    const unsigned mbar = smem_u32(smem_raw + SM_MB);

    const int cta = blockIdx.x;        // 512 CTAs
    const int b   = cta >> 6;
    const int y   = cta & 63;

    const int tid  = threadIdx.x;
    const int wrp  = tid >> 5;
    const int lane = tid & 31;
    const int ow   = wrp & 3;          // o-group: o_base = ow*64
    const int pw   = wrp >> 2;         // p-group: p_base = pw*32

    const float* xbb = x + ((long)b << 20);

    if (tid == 0) mbar_init(mbar, 1);

    // ---- one-time prep: all taps' corner indices + folded weights ----
    for (int i = tid; i < KK_ * 64; i += 256) {
        int kk = i >> 6;
        int pp = i & 63;
        int base_oy = ((b * 18 + 2 * kk) * 64 + y) * 64 + pp;
        float oy = __ldg(&coff[base_oy]);
        float ox = __ldg(&coff[base_oy + HW_]);
        float cw = __ldg(&cwt[((b * 9 + kk) * 64 + y) * 64 + pp]);
        int ky = kk / 3;
        int kx = kk - ky * 3;
        float py = (float)(y  - 1 + ky) + oy;
        float px = (float)(pp - 1 + kx) + ox;
        float fy = floorf(py), fx = floorf(px);
        int   y0 = (int)fy,    x0 = (int)fx;
        float wy1 = py - fy, wy0 = 1.0f - wy1;
        float wx1 = px - fx, wx0 = 1.0f - wx1;
        bool vy0 = (y0 >= 0)  && (y0 < H_);
        bool vy1 = (y0 >= -1) && (y0 < H_ - 1);
        bool vx0 = (x0 >= 0)  && (x0 < W_);
        bool vx1 = (x0 >= -1) && (x0 < W_ - 1);
        int yc0 = max(0, min(H_ - 1, y0));
        int yc1 = max(0, min(H_ - 1, y0 + 1));
        int xc0 = max(0, min(W_ - 1, x0));
        int xc1 = max(0, min(W_ - 1, x0 + 1));
        int s0 = (yc0 << 6) + xc0, s1 = (yc0 << 6) + xc1;
        int s2 = (yc1 << 6) + xc0, s3 = (yc1 << 6) + xc1;
        pspat[(kk << 7) + pp]      = s0 | (s1 << 16);
        pspat[(kk << 7) + 64 + pp] = s2 | (s3 << 16);
        pwgt[(kk << 8) + pp]        = (vy0 && vx0) ? cw * wy0 * wx0 : 0.0f;
        pwgt[(kk << 8) + 64 + pp]   = (vy0 && vx1) ? cw * wy0 * wx1 : 0.0f;
        pwgt[(kk << 8) + 128 + pp]  = (vy1 && vx0) ? cw * wy1 * wx0 : 0.0f;
        pwgt[(kk << 8) + 192 + pp]  = (vy1 && vx1) ? cw * wy1 * wx1 : 0.0f;
    }
    __syncthreads();

    float acc[2][8][4];
#pragma unroll
    for (int i = 0; i < 2; ++i)
#pragma unroll
        for (int j = 0; j < 8; ++j)
#pragma unroll
            for (int k = 0; k < 4; ++k) acc[i][j][k] = 0.0f;

    const int gp = tid & 63;           // gather: position 0..63
    const int gc = tid >> 6;           // gather: c sub-group 0..3

    const int a_row_off = (lane & 15);
    const int a_col_off = (lane >> 4) << 3;
    const int b_row_off = ((lane >> 4) << 3) + (lane & 7);
    const int b_col_off = ((lane >> 3) & 1) << 3;

    const unsigned w_sm_base = smem_u32(w_sm);

    unsigned ph = 0;

    // ---- prologue: stage-0 w via bulk copy, stage-0 s gathered directly ----
    if (tid == 0) {
        mbar_expect_tx(mbar, W_TILE_BYTES);
        bulk_copy(w_sm_base, (const char*)g_ws, W_TILE_BYTES, mbar);
    }
    {
        int pk01 = pspat[gp];
        int pk23 = pspat[64 + gp];
        int sp0 = pk01 & 0xFFFF, sp1 = ((unsigned)pk01) >> 16;
        int sp2 = pk23 & 0xFFFF, sp3 = ((unsigned)pk23) >> 16;
        float g0 = pwgt[gp], g1 = pwgt[64 + gp];
        float g2 = pwgt[128 + gp], g3 = pwgt[192 + gp];
        __nv_bfloat16 hv[4], lv[4];
#pragma unroll
        for (int j = 0; j < 4; ++j) {
            const float* pl = xbb + (((gc << 2) + j) << 12);
            float v = g0 * __ldg(pl + sp0) + g1 * __ldg(pl + sp1)
                    + g2 * __ldg(pl + sp2) + g3 * __ldg(pl + sp3);
            hv[j] = __float2bfloat16_rn(v);
            lv[j] = __float2bfloat16_rn(v - __bfloat162float(hv[j]));
        }
        *(uint2*)(s_sm + gp * WROW_ + (gc << 2)) =
            make_uint2(pkbf(hv[0], hv[1]), pkbf(hv[2], hv[3]));
        *(uint2*)(s_sm + S_SPL + gp * WROW_ + (gc << 2)) =
            make_uint2(pkbf(lv[0], lv[1]), pkbf(lv[2], lv[3]));
    }
    mbar_wait(mbar, ph); ph ^= 1;
    __syncthreads();

    // ---- 144 pipelined stages ----
    for (int s = 0; s < 144; ++s) {
        const __nv_bfloat16* sb = s_sm + (s & 1) * S_BUF;
        const __nv_bfloat16* wb = w_sm + (s & 1) * W_BUF;
        const int sn = s + 1;
        const int kk2 = sn >> 4;
        const int c0n = (sn & 15) << 4;

        // prefetch w(s+1): single bulk copy
        if (s < 143 && tid == 0) {
            mbar_expect_tx(mbar, W_TILE_BYTES);
            bulk_copy(w_sm_base + (unsigned)((sn & 1) * W_TILE_BYTES),
                      (const char*)g_ws + (size_t)sn * W_TILE_BYTES,
                      W_TILE_BYTES, mbar);
        }

        // next-stage gather state
        int sp0 = 0, sp1 = 0, sp2 = 0, sp3 = 0;
        float g0 = 0, g1 = 0, g2 = 0, g3 = 0;
        const float* pl_base = xbb;
        if (s < 143) {
            int pk01 = pspat[(kk2 << 7) + gp];
            int pk23 = pspat[(kk2 << 7) + 64 + gp];
            sp0 = pk01 & 0xFFFF; sp1 = ((unsigned)pk01) >> 16;
            sp2 = pk23 & 0xFFFF; sp3 = ((unsigned)pk23) >> 16;
            g0 = pwgt[(kk2 << 8) + gp];
            g1 = pwgt[(kk2 << 8) + 64 + gp];
            g2 = pwgt[(kk2 << 8) + 128 + gp];
            g3 = pwgt[(kk2 << 8) + 192 + gp];
            pl_base = xbb + ((c0n + (gc << 2)) << 12);
        }

        // A fragments (stage s)
        unsigned ah[2][4], al[2][4];
#pragma unroll
        for (int pt = 0; pt < 2; ++pt) {
            int prow = (pw << 5) + (pt << 4) + a_row_off;
            unsigned addr_h = smem_u32(sb + prow * WROW_ + a_col_off);
            unsigned addr_l = smem_u32(sb + S_SPL + prow * WROW_ + a_col_off);
            asm volatile("ldmatrix.sync.aligned.m8n8.x4.shared.b16 {%0,%1,%2,%3}, [%4];"
                : "=r"(ah[pt][0]), "=r"(ah[pt][1]), "=r"(ah[pt][2]), "=r"(ah[pt][3])
                : "r"(addr_h));
            asm volatile("ldmatrix.sync.aligned.m8n8.x4.shared.b16 {%0,%1,%2,%3}, [%4];"
                : "=r"(al[pt][0]), "=r"(al[pt][1]), "=r"(al[pt][2]), "=r"(al[pt][3])
                : "r"(addr_l));
        }

#define MMA(A, B0, B1, D) \
    asm volatile("mma.sync.aligned.m16n8k16.row.col.f32.bf16.bf16.f32 " \
        "{%0,%1,%2,%3},{%4,%5,%6,%7},{%8,%9},{%0,%1,%2,%3};" \
        : "+f"(D[0]), "+f"(D[1]), "+f"(D[2]), "+f"(D[3]) \
        : "r"(A[0]), "r"(A[1]), "r"(A[2]), "r"(A[3]), "r"(B0), "r"(B1))

#define MMA_OTP(otp_) do { \
    int orow = (ow << 6) + ((otp_) << 4) + b_row_off; \
    unsigned addr_h = smem_u32(wb + orow * WROW_ + b_col_off); \
    unsigned addr_l = smem_u32(wb + W_SPL + orow * WROW_ + b_col_off); \
    unsigned bh[4], bl[4]; \
    asm volatile("ldmatrix.sync.aligned.m8n8.x4.shared.b16 {%0,%1,%2,%3}, [%4];" \
        : "=r"(bh[0]), "=r"(bh[1]), "=r"(bh[2]), "=r"(bh[3]) : "r"(addr_h)); \
    asm volatile("ldmatrix.sync.aligned.m8n8.x4.shared.b16 {%0,%1,%2,%3}, [%4];" \
        : "=r"(bl[0]), "=r"(bl[1]), "=r"(bl[2]), "=r"(bl[3]) : "r"(addr_l)); \
    _Pragma("unroll") \
    for (int sub = 0; sub < 2; ++sub) { \
        int ot = ((otp_) << 1) + sub; \
        _Pragma("unroll") \
        for (int pt = 0; pt < 2; ++pt) { \
            float* d = acc[pt][ot]; \
            MMA(ah[pt], bh[sub * 2], bh[sub * 2 + 1], d); \
            MMA(al[pt], bh[sub * 2], bh[sub * 2 + 1], d); \
            MMA(ah[pt], bl[sub * 2], bl[sub * 2 + 1], d); \
        } \
    } \
} while (0)

        // ---- half 0: issue 8 gather loads, mma otp 0-1, combine+store ----
        float la[8];
        if (s < 143) {
#pragma unroll
            for (int i = 0; i < 2; ++i) {
                const float* pl = pl_base + (i << 12);
                la[i * 4 + 0] = __ldg(pl + sp0);
                la[i * 4 + 1] = __ldg(pl + sp1);
                la[i * 4 + 2] = __ldg(pl + sp2);
                la[i * 4 + 3] = __ldg(pl + sp3);
            }
        }
        MMA_OTP(0);
        MMA_OTP(1);
        if (s < 143) {
            __nv_bfloat16* sbn = s_sm + (sn & 1) * S_BUF;
#pragma unroll
            for (int i = 0; i < 2; ++i) {
                float v = g0 * la[i * 4] + g1 * la[i * 4 + 1]
                        + g2 * la[i * 4 + 2] + g3 * la[i * 4 + 3];
                __nv_bfloat16 hv = __float2bfloat16_rn(v);
                __nv_bfloat16 lv = __float2bfloat16_rn(v - __bfloat162float(hv));
                sbn[gp * WROW_ + (gc << 2) + i] = hv;
                sbn[S_SPL + gp * WROW_ + (gc << 2) + i] = lv;
            }
        }

        // ---- half 1: issue 8 gather loads, mma otp 2-3, combine+store ----
        float lb[8];
        if (s < 143) {
#pragma unroll
            for (int i = 0; i < 2; ++i) {
                const float* pl = pl_base + ((i + 2) << 12);
                lb[i * 4 + 0] = __ldg(pl + sp0);
                lb[i * 4 + 1] = __ldg(pl + sp1);
                lb[i * 4 + 2] = __ldg(pl + sp2);
                lb[i * 4 + 3] = __ldg(pl + sp3);
            }
        }
        MMA_OTP(2);
        MMA_OTP(3);
        if (s < 143) {
            __nv_bfloat16* sbn = s_sm + (sn & 1) * S_BUF;
#pragma unroll
            for (int i = 0; i < 2; ++i) {
                float v = g0 * lb[i * 4] + g1 * lb[i * 4 + 1]
                        + g2 * lb[i * 4 + 2] + g3 * lb[i * 4 + 3];
                __nv_bfloat16 hv = __float2bfloat16_rn(v);
                __nv_bfloat16 lv = __float2bfloat16_rn(v - __bfloat162float(hv));
                sbn[gp * WROW_ + (gc << 2) + 2 + i] = hv;
                sbn[S_SPL + gp * WROW_ + (gc << 2) + 2 + i] = lv;
            }
        }
#undef MMA_OTP
#undef MMA

        if (s < 143) { mbar_wait(mbar, ph); ph ^= 1; }
        __syncthreads();
    }

    // ---- epilogue: bias + fp32 stores ----
    const long ob_base = ((long)b << 8);
#pragma unroll
    for (int ot = 0; ot < 8; ++ot) {
        int oc = (ow << 6) + (ot << 3) + ((lane & 3) << 1);
        float b0 = __ldg(&bias[oc]);
        float b1 = __ldg(&bias[oc + 1]);
        float* o0p = out + ((ob_base + oc) << 12) + (y << 6);
        float* o1p = out + ((ob_base + oc + 1) << 12) + (y << 6);
#pragma unroll
        for (int pt = 0; pt < 2; ++pt) {
            const float* d = acc[pt][ot];
            int r0 = (pw << 5) + (pt << 4) + (lane >> 2);
            int r1 = r0 + 8;
            o0p[r0] = d[0] + b0;
            o1p[r0] = d[1] + b1;
            o0p[r1] = d[2] + b0;
            o1p[r1] = d[3] + b1;
        }
    }
}

// ---------------------------------------------------------------------------
// Launch: inputs per metadata order: input, coord_offset, coord_weight, weight, bias
// ---------------------------------------------------------------------------
extern "C" void kernel_launch(void* const* d_in, const int* in_sizes, int n_in,
                              void* d_out, int out_size) {
    const float* x    = (const float*)d_in[0];
    const float* coff = (const float*)d_in[1];
    const float* cwt  = (const float*)d_in[2];
    const float* wt   = (const float*)d_in[3];
    const float* bias = (const float*)d_in[4];
    float* out = (float*)d_out;

    static int smem_set = 0;
    if (!smem_set) {
        cudaFuncSetAttribute(dcn_main,
                             cudaFuncAttributeMaxDynamicSharedMemorySize,
                             SM_TOT);
        smem_set = 1;
    }

    int n_ws = KK_ * 16 * 2 * O_ * WROW_;
    dcn_split_w<<<(n_ws + 255) / 256, 256>>>(wt);
    dcn_main<<<B_ * H_, 256, SM_TOT>>>(x, coff, cwt, bias, out);
}